// round 2
// baseline (speedup 1.0000x reference)
#include <cuda_runtime.h>

#define BS 4
#define NQ 1024
#define NK 1024
#define QD 128
#define VD 128
#define HID 64

#define TQ 16
#define TK 128
#define ATT_THREADS 128
#define ATT_SMEM_FLOATS (TQ*NK + HID*TK + TQ*HID + HID + TQ)
#define ATT_SMEM_BYTES (ATT_SMEM_FLOATS * 4)

// Scratch (allocation-free rule: __device__ globals)
__device__ float g_q [BS * NQ * HID];   // [b][q][h]
__device__ float g_kT[BS * HID * NK];   // [b][h][k]  (transposed for conflict-free smem staging)

__device__ __forceinline__ float tanh_fast(float x) {
    float y;
    asm("tanh.approx.f32 %0, %1;" : "=f"(y) : "f"(x));
    return y;
}

// ---------------------------------------------------------------------------
// Projection kernel: q = queries @ W_q  -> g_q,   kT = (keys @ W_k)^T -> g_kT
// grid.x = 512: [0,256) -> q tiles, [256,512) -> k tiles. 16 rows/block.
// ---------------------------------------------------------------------------
#define PR 16
__global__ __launch_bounds__(256) void proj_kernel(
    const float* __restrict__ queries, const float* __restrict__ keys,
    const float* __restrict__ W_q, const float* __restrict__ W_k)
{
    __shared__ float Ws[HID][QD + 4];   // W transposed: Ws[h][d], pad keeps float4 reads conflict-free
    __shared__ float xs[PR][QD];

    int bid   = blockIdx.x;
    int which = bid >> 8;               // 0 = q, 1 = k
    int tile  = bid & 255;
    int b     = tile >> 6;              // 64 tiles per batch
    int r0    = (tile & 63) * PR;

    const float* X = which ? keys : queries;
    const float* W = which ? W_k  : W_q;
    int t = threadIdx.x;

    for (int idx = t; idx < QD * HID; idx += 256) {
        int d = idx >> 6, h = idx & 63;
        Ws[h][d] = W[idx];              // coalesced read, transposed smem write
    }
    const float* xbase = X + ((size_t)b * NQ + r0) * QD;
    for (int idx = t; idx < PR * QD; idx += 256)
        xs[idx >> 7][idx & 127] = xbase[idx];
    __syncthreads();

    int h  = t & 63;
    int rg = t >> 6;                    // 0..3, rows handled: rg, rg+4, rg+8, rg+12
    float acc[4] = {0.f, 0.f, 0.f, 0.f};
    #pragma unroll 8
    for (int d = 0; d < QD; d += 4) {
        float4 w4 = *(const float4*)&Ws[h][d];
        #pragma unroll
        for (int i = 0; i < 4; i++) {
            float4 x4 = *(const float4*)&xs[rg + 4 * i][d];
            acc[i] = fmaf(w4.x, x4.x, fmaf(w4.y, x4.y,
                     fmaf(w4.z, x4.z, fmaf(w4.w, x4.w, acc[i]))));
        }
    }

    if (which == 0) {
        #pragma unroll
        for (int i = 0; i < 4; i++)
            g_q[((size_t)b * NQ + r0 + rg + 4 * i) * HID + h] = acc[i];
    } else {
        #pragma unroll
        for (int i = 0; i < 4; i++)
            g_kT[((size_t)b * HID + h) * NK + r0 + rg + 4 * i] = acc[i];
    }
}

// ---------------------------------------------------------------------------
// Fused attention kernel: block = (b, 16-query tile). Thread t owns key column
// t of each 128-key tile. Scores for all 1024 keys held in smem -> two-pass
// softmax -> PV from smem-staged V tiles.
// ---------------------------------------------------------------------------
__global__ __launch_bounds__(ATT_THREADS) void att_kernel(
    const float* __restrict__ values, const float* __restrict__ w_v,
    float* __restrict__ out)
{
    extern __shared__ float sm[];
    float* ss   = sm;                       // [TQ][NK]      scores -> exp(scores)
    float* ks   = sm + TQ * NK;             // [HID][TK]     k tile (reused as V tile [64][VD])
    float* qs   = ks + HID * TK;            // [TQ][HID]
    float* wvs  = qs + TQ * HID;            // [HID]
    float* sinv = wvs + HID;                // [TQ]

    int t  = threadIdx.x;
    int b  = blockIdx.y;
    int q0 = blockIdx.x * TQ;

    {
        const float* qb = g_q + ((size_t)b * NQ + q0) * HID;
        for (int i = t; i < TQ * HID; i += ATT_THREADS) qs[i] = qb[i];
    }
    if (t < HID) wvs[t] = w_v[t];
    __syncthreads();

    // ---- Pass A: scores -------------------------------------------------
    const float* kTb = g_kT + (size_t)b * HID * NK;
    for (int kt = 0; kt < NK / TK; ++kt) {
        #pragma unroll 8
        for (int h = 0; h < HID; ++h)
            ks[h * TK + t] = kTb[h * NK + kt * TK + t];
        __syncthreads();

        float acc[TQ];
        #pragma unroll
        for (int qi = 0; qi < TQ; ++qi) acc[qi] = 0.f;

        #pragma unroll 2
        for (int h = 0; h < HID; h += 4) {
            float k0 = ks[(h + 0) * TK + t];
            float k1 = ks[(h + 1) * TK + t];
            float k2 = ks[(h + 2) * TK + t];
            float k3 = ks[(h + 3) * TK + t];
            float4 w4 = *(const float4*)&wvs[h];
            #pragma unroll
            for (int qi = 0; qi < TQ; ++qi) {
                float4 q4 = *(const float4*)&qs[qi * HID + h];
                float s = acc[qi];
                s = fmaf(w4.x, tanh_fast(q4.x + k0), s);
                s = fmaf(w4.y, tanh_fast(q4.y + k1), s);
                s = fmaf(w4.z, tanh_fast(q4.z + k2), s);
                s = fmaf(w4.w, tanh_fast(q4.w + k3), s);
                acc[qi] = s;
            }
        }
        #pragma unroll
        for (int qi = 0; qi < TQ; ++qi)
            ss[qi * NK + kt * TK + t] = acc[qi];
        __syncthreads();
    }

    // ---- Pass B: softmax (4 warps, 16 rows) -----------------------------
    int warp = t >> 5, lane = t & 31;
    for (int qi = warp; qi < TQ; qi += ATT_THREADS / 32) {
        float* row = ss + qi * NK;
        float m = -1e30f;
        for (int i = lane; i < NK; i += 32) m = fmaxf(m, row[i]);
        #pragma unroll
        for (int o = 16; o > 0; o >>= 1) m = fmaxf(m, __shfl_xor_sync(0xffffffffu, m, o));
        float sum = 0.f;
        for (int i = lane; i < NK; i += 32) {
            float e = __expf(row[i] - m);
            row[i] = e;
            sum += e;
        }
        #pragma unroll
        for (int o = 16; o > 0; o >>= 1) sum += __shfl_xor_sync(0xffffffffu, sum, o);
        if (lane == 0) sinv[qi] = 1.f / sum;
    }
    __syncthreads();

    // ---- Pass C: out = attn @ V  (thread t owns output column t) --------
    float* vs = ks;                         // reuse k-tile smem as [64][VD]
    float o[TQ];
    #pragma unroll
    for (int qi = 0; qi < TQ; ++qi) o[qi] = 0.f;

    const float* vb = values + (size_t)b * NK * VD;
    for (int jt = 0; jt < NK / 64; ++jt) {
        __syncthreads();                    // previous tile fully consumed
        for (int i = t; i < 64 * VD; i += ATT_THREADS)
            vs[i] = vb[(size_t)jt * 64 * VD + i];
        __syncthreads();
        #pragma unroll 2
        for (int j = 0; j < 64; j += 4) {
            float v0 = vs[(j + 0) * VD + t];
            float v1 = vs[(j + 1) * VD + t];
            float v2 = vs[(j + 2) * VD + t];
            float v3 = vs[(j + 3) * VD + t];
            #pragma unroll
            for (int qi = 0; qi < TQ; ++qi) {
                float4 a4 = *(const float4*)&ss[qi * NK + jt * 64 + j];
                float s = o[qi];
                s = fmaf(a4.x, v0, s);
                s = fmaf(a4.y, v1, s);
                s = fmaf(a4.z, v2, s);
                s = fmaf(a4.w, v3, s);
                o[qi] = s;
            }
        }
    }

    float* ob = out + ((size_t)b * NQ + q0) * VD;
    #pragma unroll
    for (int qi = 0; qi < TQ; ++qi)
        ob[qi * VD + t] = o[qi] * sinv[qi];
}

// ---------------------------------------------------------------------------
extern "C" void kernel_launch(void* const* d_in, const int* in_sizes, int n_in,
                              void* d_out, int out_size)
{
    const float* queries = (const float*)d_in[0];
    const float* keys    = (const float*)d_in[1];
    const float* values  = (const float*)d_in[2];
    const float* W_q     = (const float*)d_in[3];
    const float* W_k     = (const float*)d_in[4];
    const float* w_v     = (const float*)d_in[5];
    float* out = (float*)d_out;

    // Opt-in smem (idempotent, not a stream op -> capture-safe)
    cudaFuncSetAttribute(att_kernel, cudaFuncAttributeMaxDynamicSharedMemorySize,
                         ATT_SMEM_BYTES);

    proj_kernel<<<512, 256>>>(queries, keys, W_q, W_k);
    att_kernel<<<dim3(NQ / TQ, BS), ATT_THREADS, ATT_SMEM_BYTES>>>(values, w_v, out);
}